// round 10
// baseline (speedup 1.0000x reference)
#include <cuda_runtime.h>
#include <cuda_bf16.h>
#include <cstdint>

// SymmetryAwareLossLoop: mean over B of min over (C,S) geodesic angle.
// tr(R_pred (R_s R_gt)^T) = <R_s, P>, P = R_pred R_gt^T; P622 traces collapse
// to closed form (+/- pairs); acos monotone -> one acosf per batch group.
//
// R10: grid=148 (one CTA per SM, bytes/SM balanced to 1%) kills the 2:1
// per-SM TMA-service imbalance of grid=256/512. Whole per-CTA slab (~128KB)
// lives in smem at once: 4 chunked bulk copies + gt, all issued at t=0 with
// per-chunk mbarriers; compute overlaps arrival. Fused fence+counter tail.

#define B_TOTAL   16384
#define C_CAND    32
#define THREADS   256
#define NBLOCKS   148
#define CH_BATCH  32
#define CH_BYTES  (CH_BATCH * C_CAND * 9 * 4)     // 36864
#define NCHUNK    4                               // ceil(111/32)
#define GT_BUF    4608                            // >= 111*36 + 16 slack
#define SMEM_DYN  (NCHUNK * CH_BYTES + GT_BUF)    // 152064

__device__ float        g_partials[NBLOCKS];
__device__ unsigned int g_count = 0;

extern __shared__ unsigned char s_dyn[];

__global__ __launch_bounds__(THREADS)
void sym_loss_fused(const float* __restrict__ pred,   // (B, C, 3, 3)
                    const float* __restrict__ gt,     // (B, 3, 3)
                    float* __restrict__ out)
{
    __shared__ alignas(8) unsigned long long s_mbar[NCHUNK];
    __shared__ float swarp[THREADS / 32];
    __shared__ bool  sIsLast;

    const int tid = threadIdx.x;
    const int cta = blockIdx.x;

    // Balanced contiguous batch range for this CTA: [bs, be)
    const int bs = (int)(((long long)B_TOTAL * cta) / NBLOCKS);
    const int be = (int)(((long long)B_TOTAL * (cta + 1)) / NBLOCKS);
    const int nb = be - bs;                                  // 110 or 111

    // 16B-aligned gt source window covering [bs*36, be*36)
    const uint32_t gA   = ((uint32_t)(bs * 36)) & ~15u;
    const uint32_t gLen = ((uint32_t)(be * 36) - gA + 15u) & ~15u;

    const uint32_t mb0 = (uint32_t)__cvta_generic_to_shared(&s_mbar[0]);

    if (tid == 0) {
        #pragma unroll
        for (int k = 0; k < NCHUNK; ++k)
            asm volatile("mbarrier.init.shared.b64 [%0], %1;"
                         :: "r"(mb0 + 8u * k), "r"(1u) : "memory");
    }
    __syncthreads();   // mbarriers visible before waits / TMA

    if (tid == 0) {
        const uint32_t dp = (uint32_t)__cvta_generic_to_shared(s_dyn);
        const uint32_t dg = dp + NCHUNK * CH_BYTES;
        const char* srcp = (const char*)pred + (size_t)bs * 1152;
        const char* srcg = (const char*)gt + gA;

        #pragma unroll
        for (int k = 0; k < NCHUNK; ++k) {
            const int nbk = min(CH_BATCH, nb - k * CH_BATCH);    // >=14
            const uint32_t bytes = (uint32_t)(nbk * 1152);
            const uint32_t extra = (k == 0) ? gLen : 0u;
            asm volatile("mbarrier.arrive.expect_tx.shared.b64 _, [%0], %1;"
                         :: "r"(mb0 + 8u * k), "r"(bytes + extra) : "memory");
            asm volatile("cp.async.bulk.shared::cta.global.mbarrier::complete_tx::bytes [%0], [%1], %2, [%3];"
                         :: "r"(dp + k * CH_BYTES), "l"(srcp + (size_t)k * CH_BYTES),
                            "r"(bytes), "r"(mb0 + 8u * k) : "memory");
            if (k == 0)
                asm volatile("cp.async.bulk.shared::cta.global.mbarrier::complete_tx::bytes [%0], [%1], %2, [%3];"
                             :: "r"(dg), "l"(srcg), "r"(gLen), "r"(mb0) : "memory");
        }
    }

    const float h = 0.8660254037844386f;   // sin(pi/3)
    float thetaAcc = 0.0f;                 // per-lane, per-group accumulator

    #pragma unroll
    for (int k = 0; k < NCHUNK; ++k) {
        asm volatile(
            "{\n\t"
            ".reg .pred P;\n\t"
            "WAIT_%=:\n\t"
            "mbarrier.try_wait.parity.shared.b64 P, [%0], %1;\n\t"
            "@P bra DONE_%=;\n\t"
            "bra WAIT_%=;\n\t"
            "DONE_%=:\n\t"
            "}"
            :: "r"(mb0 + 8u * k), "r"(0u) : "memory");

        const int nbk    = min(CH_BATCH, nb - k * CH_BATCH);
        const bool active = (tid < nbk * 8);      // group-uniform (8 lanes/batch)

        // thread = quad of 4 candidates; 8 quads per batch
        const float4* __restrict__ sp =
            reinterpret_cast<const float4*>(s_dyn + k * CH_BYTES + tid * 144);
        float4 v[9];
        #pragma unroll
        for (int i = 0; i < 9; ++i) v[i] = sp[i];
        const float* a = reinterpret_cast<const float*>(v);

        const int bGlob = bs + k * CH_BATCH + (tid >> 3);
        const float* __restrict__ gp = reinterpret_cast<const float*>(
            s_dyn + NCHUNK * CH_BYTES + ((uint32_t)(bGlob * 36) - gA));
        float gr[9];
        #pragma unroll
        for (int i = 0; i < 9; ++i) gr[i] = gp[i];

        float maxtr = -4.0f;
        #pragma unroll
        for (int j = 0; j < 4; ++j) {
            const float p0 = a[9*j+0], p1 = a[9*j+1], p2 = a[9*j+2];
            const float p3 = a[9*j+3], p4 = a[9*j+4], p5 = a[9*j+5];
            const float p6 = a[9*j+6], p7 = a[9*j+7], p8 = a[9*j+8];

            const float P00 = fmaf(p0, gr[0], fmaf(p1, gr[1], p2 * gr[2]));
            const float P01 = fmaf(p0, gr[3], fmaf(p1, gr[4], p2 * gr[5]));
            const float P10 = fmaf(p3, gr[0], fmaf(p4, gr[1], p5 * gr[2]));
            const float P11 = fmaf(p3, gr[3], fmaf(p4, gr[4], p5 * gr[5]));
            const float P22 = fmaf(p6, gr[6], fmaf(p7, gr[7], p8 * gr[8]));

            const float A  = P00 + P11;
            const float Bv = P10 - P01;
            const float D  = P00 - P11;
            const float E  = P01 + P10;

            const float mz = fmaxf(fabsf(A),
                             fmaxf(fabsf(fmaf(h, Bv,  0.5f * A)),
                                   fabsf(fmaf(h, Bv, -0.5f * A))));
            const float m2 = fmaxf(fabsf(D),
                             fmaxf(fabsf(fmaf(h, E,  0.5f * D)),
                                   fabsf(fmaf(h, E, -0.5f * D))));

            maxtr = fmaxf(maxtr, fmaxf(mz + P22, m2 - P22));
        }

        // max over the 8 lanes owning this batch (xor-closed subgroups)
        #pragma unroll
        for (int off = 1; off < 8; off <<= 1)
            maxtr = fmaxf(maxtr, __shfl_xor_sync(0xFFFFFFFFu, maxtr, off));

        float cosv = (maxtr - 1.0f) * 0.5f;
        cosv = fminf(fmaxf(cosv, -1.0f + 1e-7f), 1.0f - 1e-7f);
        thetaAcc += active ? acosf(cosv) : 0.0f;   // inactive groups add 0
    }

    // xor offsets {8,16} hit each 8-lane group exactly once -> per-warp sum
    // over its 4 batch-groups across all chunks; no overcount.
    #pragma unroll
    for (int off = 8; off < 32; off <<= 1)
        thetaAcc += __shfl_xor_sync(0xFFFFFFFFu, thetaAcc, off);

    if ((tid & 31) == 0) swarp[tid >> 5] = thetaAcc;
    __syncthreads();

    if (tid == 0) {
        float s = 0.0f;
        #pragma unroll
        for (int i = 0; i < THREADS / 32; ++i) s += swarp[i];
        g_partials[cta] = s;
        __threadfence();
        unsigned int old = atomicAdd(&g_count, 1u);
        sIsLast = (old == (unsigned int)(NBLOCKS - 1));
    }
    __syncthreads();

    if (sIsLast) {
        __threadfence();   // acquire: see all blocks' partials
        float s = (tid < NBLOCKS) ? g_partials[tid] : 0.0f;
        #pragma unroll
        for (int off = 16; off > 0; off >>= 1)
            s += __shfl_xor_sync(0xFFFFFFFFu, s, off);
        if ((tid & 31) == 0) swarp[tid >> 5] = s;
        __syncthreads();
        if (tid == 0) {
            float t = 0.0f;
            #pragma unroll
            for (int i = 0; i < THREADS / 32; ++i) t += swarp[i];
            out[0] = t / (float)B_TOTAL;
            g_count = 0;                            // reset for next replay
        }
    }
}

extern "C" void kernel_launch(void* const* d_in, const int* in_sizes, int n_in,
                              void* d_out, int out_size)
{
    const float* pred = (const float*)d_in[0];   // (B, C, 3, 3)
    const float* gt   = (const float*)d_in[1];   // (B, 3, 3)
    // d_in[2] = rot_mats: P622 rotations, folded into closed-form constants.
    float* out = (float*)d_out;

    // Idempotent attribute set (not a stream op): 148KB+ dynamic smem.
    cudaFuncSetAttribute(sym_loss_fused,
                         cudaFuncAttributeMaxDynamicSharedMemorySize, SMEM_DYN);

    sym_loss_fused<<<NBLOCKS, THREADS, SMEM_DYN>>>(pred, gt, out);
}

// round 13
// speedup vs baseline: 1.9368x; 1.9368x over previous
#include <cuda_runtime.h>
#include <cuda_bf16.h>
#include <cstdint>

// SymmetryAwareLossLoop: mean over B of min over (C,S) geodesic angle.
// tr(R_pred (R_s R_gt)^T) = <R_s, P>, P = R_pred R_gt^T; P622 traces collapse
// to closed form (+/- pairs); acos monotone -> one acosf per batch group.
//
// R13 = R11 (grid=296, exactly 2 CTAs/SM, balanced 55/56 batches per CTA,
// 2-chunk TMA all issued at t=0, fused fence+counter tail) with the R12
// illegal-access fixed: chunk STRIDE padded to 32 batches and GT_BUF to 4KB
// so the unconditional 256-thread smem reads (inactive lanes masked by
// `active ? : 0`) always land inside allocated smem.

#define B_TOTAL   16384
#define C_CAND    32
#define THREADS   256
#define NBLOCKS   296
#define CH_BATCH  28                              // batches copied per chunk
#define CH_STRIDE (32 * C_CAND * 9 * 4)           // 36864: padded buffer stride
#define GT_BUF    4096                            // covers bGlob up to bs+59
#define SMEM_DYN  (2 * CH_STRIDE + GT_BUF)        // 77824 (~76KB, 2 CTAs/SM)

__device__ float        g_partials[NBLOCKS];
__device__ unsigned int g_count = 0;

extern __shared__ unsigned char s_dyn[];

__global__ __launch_bounds__(THREADS)
void sym_loss_fused(const float* __restrict__ pred,   // (B, C, 3, 3)
                    const float* __restrict__ gt,     // (B, 3, 3)
                    float* __restrict__ out)
{
    __shared__ alignas(8) unsigned long long s_mbar[2];
    __shared__ float swarp[THREADS / 32];
    __shared__ bool  sIsLast;

    const int tid = threadIdx.x;
    const int cta = blockIdx.x;

    // Balanced contiguous batch range [bs, be): 55 or 56 batches per CTA.
    const int bs = (int)(((long long)B_TOTAL * cta) / NBLOCKS);
    const int be = (int)(((long long)B_TOTAL * (cta + 1)) / NBLOCKS);
    const int nb = be - bs;

    // 16B-aligned gt source window (bytes) covering [bs*36, be*36)
    const uint32_t gA   = ((uint32_t)(bs * 36)) & ~15u;
    const uint32_t gLen = ((uint32_t)(be * 36) - gA + 15u) & ~15u;   // <= 2048

    const uint32_t mb0 = (uint32_t)__cvta_generic_to_shared(&s_mbar[0]);
    const uint32_t mb1 = mb0 + 8u;

    if (tid == 0) {
        asm volatile("mbarrier.init.shared.b64 [%0], %1;" :: "r"(mb0), "r"(1u) : "memory");
        asm volatile("mbarrier.init.shared.b64 [%0], %1;" :: "r"(mb1), "r"(1u) : "memory");
    }
    __syncthreads();   // mbarriers visible before waits / TMA

    if (tid == 0) {
        const uint32_t dp = (uint32_t)__cvta_generic_to_shared(s_dyn);
        const uint32_t dg = dp + 2 * CH_STRIDE;
        const char* srcp = (const char*)pred + (size_t)bs * 1152;
        const char* srcg = (const char*)gt + gA;

        const uint32_t bytes0 = (uint32_t)(CH_BATCH * 1152);          // 32256
        const uint32_t bytes1 = (uint32_t)((nb - CH_BATCH) * 1152);   // 27/28 batches

        // chunk 0 + gt on mbar0; chunk 1 on mbar1. All in flight at t=0.
        asm volatile("mbarrier.arrive.expect_tx.shared.b64 _, [%0], %1;"
                     :: "r"(mb0), "r"(bytes0 + gLen) : "memory");
        asm volatile("cp.async.bulk.shared::cta.global.mbarrier::complete_tx::bytes [%0], [%1], %2, [%3];"
                     :: "r"(dp), "l"(srcp), "r"(bytes0), "r"(mb0) : "memory");
        asm volatile("cp.async.bulk.shared::cta.global.mbarrier::complete_tx::bytes [%0], [%1], %2, [%3];"
                     :: "r"(dg), "l"(srcg), "r"(gLen), "r"(mb0) : "memory");

        asm volatile("mbarrier.arrive.expect_tx.shared.b64 _, [%0], %1;"
                     :: "r"(mb1), "r"(bytes1) : "memory");
        asm volatile("cp.async.bulk.shared::cta.global.mbarrier::complete_tx::bytes [%0], [%1], %2, [%3];"
                     :: "r"(dp + CH_STRIDE), "l"(srcp + (size_t)CH_BATCH * 1152),
                        "r"(bytes1), "r"(mb1) : "memory");
    }

    const float h = 0.8660254037844386f;   // sin(pi/3)
    float thetaAcc = 0.0f;

    #pragma unroll
    for (int k = 0; k < 2; ++k) {
        const uint32_t mb = k ? mb1 : mb0;
        asm volatile(
            "{\n\t"
            ".reg .pred P;\n\t"
            "WAIT_%=:\n\t"
            "mbarrier.try_wait.parity.shared.b64 P, [%0], %1;\n\t"
            "@P bra DONE_%=;\n\t"
            "bra WAIT_%=;\n\t"
            "DONE_%=:\n\t"
            "}"
            :: "r"(mb), "r"(0u) : "memory");

        const int  nbk    = k ? (nb - CH_BATCH) : CH_BATCH;
        const bool active = (tid < nbk * 8);      // group-uniform (8 lanes/batch)

        // thread = quad of 4 candidates; 8 quads per batch. Reads beyond the
        // copied region stay inside the padded 36864B buffer (values unused).
        const float4* __restrict__ sp =
            reinterpret_cast<const float4*>(s_dyn + k * CH_STRIDE + tid * 144);
        float4 v[9];
        #pragma unroll
        for (int i = 0; i < 9; ++i) v[i] = sp[i];
        const float* a = reinterpret_cast<const float*>(v);

        const int bGlob = bs + k * CH_BATCH + (tid >> 3);   // may exceed be-1
        const float* __restrict__ gp = reinterpret_cast<const float*>(
            s_dyn + 2 * CH_STRIDE + ((uint32_t)(bGlob * 36) - gA));   // < 4096B
        float gr[9];
        #pragma unroll
        for (int i = 0; i < 9; ++i) gr[i] = gp[i];

        float maxtr = -4.0f;
        #pragma unroll
        for (int j = 0; j < 4; ++j) {
            const float p0 = a[9*j+0], p1 = a[9*j+1], p2 = a[9*j+2];
            const float p3 = a[9*j+3], p4 = a[9*j+4], p5 = a[9*j+5];
            const float p6 = a[9*j+6], p7 = a[9*j+7], p8 = a[9*j+8];

            const float P00 = fmaf(p0, gr[0], fmaf(p1, gr[1], p2 * gr[2]));
            const float P01 = fmaf(p0, gr[3], fmaf(p1, gr[4], p2 * gr[5]));
            const float P10 = fmaf(p3, gr[0], fmaf(p4, gr[1], p5 * gr[2]));
            const float P11 = fmaf(p3, gr[3], fmaf(p4, gr[4], p5 * gr[5]));
            const float P22 = fmaf(p6, gr[6], fmaf(p7, gr[7], p8 * gr[8]));

            const float A  = P00 + P11;
            const float Bv = P10 - P01;
            const float D  = P00 - P11;
            const float E  = P01 + P10;

            const float mz = fmaxf(fabsf(A),
                             fmaxf(fabsf(fmaf(h, Bv,  0.5f * A)),
                                   fabsf(fmaf(h, Bv, -0.5f * A))));
            const float m2 = fmaxf(fabsf(D),
                             fmaxf(fabsf(fmaf(h, E,  0.5f * D)),
                                   fabsf(fmaf(h, E, -0.5f * D))));

            maxtr = fmaxf(maxtr, fmaxf(mz + P22, m2 - P22));
        }

        // max over the 8 lanes owning this batch (xor-closed subgroups)
        #pragma unroll
        for (int off = 1; off < 8; off <<= 1)
            maxtr = fmaxf(maxtr, __shfl_xor_sync(0xFFFFFFFFu, maxtr, off));

        float cosv = (maxtr - 1.0f) * 0.5f;
        cosv = fminf(fmaxf(cosv, -1.0f + 1e-7f), 1.0f - 1e-7f);
        thetaAcc += active ? acosf(cosv) : 0.0f;   // inactive groups add 0
    }

    // xor offsets {8,16} hit each 8-lane group exactly once -> per-warp sum
    // over its 4 batch-groups across both chunks; no overcount.
    #pragma unroll
    for (int off = 8; off < 32; off <<= 1)
        thetaAcc += __shfl_xor_sync(0xFFFFFFFFu, thetaAcc, off);

    if ((tid & 31) == 0) swarp[tid >> 5] = thetaAcc;
    __syncthreads();

    if (tid == 0) {
        float s = 0.0f;
        #pragma unroll
        for (int i = 0; i < THREADS / 32; ++i) s += swarp[i];
        g_partials[cta] = s;
        __threadfence();
        unsigned int old = atomicAdd(&g_count, 1u);
        sIsLast = (old == (unsigned int)(NBLOCKS - 1));
    }
    __syncthreads();

    if (sIsLast) {
        __threadfence();   // acquire: see all blocks' partials
        float s = g_partials[tid];
        if (tid + THREADS < NBLOCKS) s += g_partials[tid + THREADS];
        #pragma unroll
        for (int off = 16; off > 0; off >>= 1)
            s += __shfl_xor_sync(0xFFFFFFFFu, s, off);
        if ((tid & 31) == 0) swarp[tid >> 5] = s;
        __syncthreads();
        if (tid == 0) {
            float t = 0.0f;
            #pragma unroll
            for (int i = 0; i < THREADS / 32; ++i) t += swarp[i];
            out[0] = t / (float)B_TOTAL;
            g_count = 0;                            // reset for next replay
        }
    }
}

extern "C" void kernel_launch(void* const* d_in, const int* in_sizes, int n_in,
                              void* d_out, int out_size)
{
    const float* pred = (const float*)d_in[0];   // (B, C, 3, 3)
    const float* gt   = (const float*)d_in[1];   // (B, 3, 3)
    // d_in[2] = rot_mats: P622 rotations, folded into closed-form constants.
    float* out = (float*)d_out;

    // Idempotent attribute set (not a stream op): 76KB dynamic smem.
    cudaFuncSetAttribute(sym_loss_fused,
                         cudaFuncAttributeMaxDynamicSharedMemorySize, SMEM_DYN);

    sym_loss_fused<<<NBLOCKS, THREADS, SMEM_DYN>>>(pred, gt, out);
}

// round 14
// speedup vs baseline: 2.0554x; 1.0612x over previous
#include <cuda_runtime.h>
#include <cuda_bf16.h>
#include <cstdint>

// SymmetryAwareLossLoop: mean over B of min over (C,S) geodesic angle.
// tr(R_pred (R_s R_gt)^T) = <R_s, P>, P = R_pred R_gt^T; P622 traces collapse
// to closed form (+/- pairs); acos monotone -> one acosf per batch group.
//
// R14 = R8 (best wall: 8.70us; grid=256, 64 batches/CTA, 2x32-batch TMA
// chunks all issued at t=0, fused fence+counter tail) + smem-carveout pin
// (avoid per-replay carveout reconfig; cf. R10's >128KB cliff) + __ldg tail.
// Evidence says we are near the environment floor: DRAM busy only ~26% of
// the 9.5us window at near-peak burst rate; the rest is ramp/latency/fixed
// overhead (a trivial grid=1 kernel measured 4.26us in R1).

#define B_TOTAL   16384
#define C_CAND    32
#define THREADS   256
#define NBLOCKS   256
#define BATCH_PC  32                                  // batches per chunk
#define CHUNK_BYTES (BATCH_PC * C_CAND * 9 * 4)       // 36864
#define GT_BYTES    (2 * BATCH_PC * 9 * 4)            // 2304 (64 batches)
#define SMEM_DYN    (2 * CHUNK_BYTES + GT_BYTES)      // 76032

__device__ float        g_partials[NBLOCKS];
__device__ unsigned int g_count = 0;

extern __shared__ unsigned char s_dyn[];

__global__ __launch_bounds__(THREADS)
void sym_loss_fused(const float* __restrict__ pred,   // (B, C, 3, 3)
                    const float* __restrict__ gt,     // (B, 3, 3)
                    float* __restrict__ out)
{
    __shared__ alignas(8) unsigned long long s_mbar[2];
    __shared__ float swarp[THREADS / 32];
    __shared__ bool  sIsLast;

    const int tid = threadIdx.x;
    const int cb  = blockIdx.x;

    const uint32_t mb0 = (uint32_t)__cvta_generic_to_shared(&s_mbar[0]);
    const uint32_t mb1 = mb0 + 8u;

    if (tid == 0) {
        asm volatile("mbarrier.init.shared.b64 [%0], %1;" :: "r"(mb0), "r"(1u) : "memory");
        asm volatile("mbarrier.init.shared.b64 [%0], %1;" :: "r"(mb1), "r"(1u) : "memory");
    }
    __syncthreads();   // mbarriers visible before anyone waits

    if (tid == 0) {
        const uint32_t dp = (uint32_t)__cvta_generic_to_shared(s_dyn);
        const uint32_t dg = dp + 2 * CHUNK_BYTES;
        const float* srcp = pred + (size_t)cb * 2 * (CHUNK_BYTES / 4);
        const float* srcg = gt   + (size_t)cb * (GT_BYTES / 4);

        // chunk 0 + gt on mbar0; chunk 1 on mbar1. All in flight at t=0.
        asm volatile("mbarrier.arrive.expect_tx.shared.b64 _, [%0], %1;"
                     :: "r"(mb0), "r"((uint32_t)(CHUNK_BYTES + GT_BYTES)) : "memory");
        asm volatile("cp.async.bulk.shared::cta.global.mbarrier::complete_tx::bytes [%0], [%1], %2, [%3];"
                     :: "r"(dp), "l"(srcp), "r"((uint32_t)CHUNK_BYTES), "r"(mb0) : "memory");
        asm volatile("cp.async.bulk.shared::cta.global.mbarrier::complete_tx::bytes [%0], [%1], %2, [%3];"
                     :: "r"(dg), "l"(srcg), "r"((uint32_t)GT_BYTES), "r"(mb0) : "memory");

        asm volatile("mbarrier.arrive.expect_tx.shared.b64 _, [%0], %1;"
                     :: "r"(mb1), "r"((uint32_t)CHUNK_BYTES) : "memory");
        asm volatile("cp.async.bulk.shared::cta.global.mbarrier::complete_tx::bytes [%0], [%1], %2, [%3];"
                     :: "r"(dp + CHUNK_BYTES), "l"(srcp + CHUNK_BYTES / 4),
                        "r"((uint32_t)CHUNK_BYTES), "r"(mb1) : "memory");
    }

    const float h = 0.8660254037844386f;   // sin(pi/3)
    float thetaSum = 0.0f;

    #pragma unroll
    for (int k = 0; k < 2; ++k) {
        const uint32_t mb = k ? mb1 : mb0;
        asm volatile(
            "{\n\t"
            ".reg .pred P;\n\t"
            "WAIT_%=:\n\t"
            "mbarrier.try_wait.parity.shared.b64 P, [%0], %1;\n\t"
            "@P bra DONE_%=;\n\t"
            "bra WAIT_%=;\n\t"
            "DONE_%=:\n\t"
            "}"
            :: "r"(mb), "r"(0u) : "memory");

        // thread = quad of 4 candidates; chunk = 32 batches = 256 quads.
        const float4* __restrict__ sp =
            reinterpret_cast<const float4*>(s_dyn + k * CHUNK_BYTES + tid * 144);
        float4 v[9];
        #pragma unroll
        for (int i = 0; i < 9; ++i) v[i] = sp[i];
        const float* a = reinterpret_cast<const float*>(v);

        const float* __restrict__ gp = reinterpret_cast<const float*>(
            s_dyn + 2 * CHUNK_BYTES + (k * BATCH_PC + (tid >> 3)) * 36);
        float gr[9];
        #pragma unroll
        for (int i = 0; i < 9; ++i) gr[i] = gp[i];

        float maxtr = -4.0f;
        #pragma unroll
        for (int j = 0; j < 4; ++j) {
            const float p0 = a[9*j+0], p1 = a[9*j+1], p2 = a[9*j+2];
            const float p3 = a[9*j+3], p4 = a[9*j+4], p5 = a[9*j+5];
            const float p6 = a[9*j+6], p7 = a[9*j+7], p8 = a[9*j+8];

            const float P00 = fmaf(p0, gr[0], fmaf(p1, gr[1], p2 * gr[2]));
            const float P01 = fmaf(p0, gr[3], fmaf(p1, gr[4], p2 * gr[5]));
            const float P10 = fmaf(p3, gr[0], fmaf(p4, gr[1], p5 * gr[2]));
            const float P11 = fmaf(p3, gr[3], fmaf(p4, gr[4], p5 * gr[5]));
            const float P22 = fmaf(p6, gr[6], fmaf(p7, gr[7], p8 * gr[8]));

            const float A  = P00 + P11;
            const float Bv = P10 - P01;
            const float D  = P00 - P11;
            const float E  = P01 + P10;

            const float mz = fmaxf(fabsf(A),
                             fmaxf(fabsf(fmaf(h, Bv,  0.5f * A)),
                                   fabsf(fmaf(h, Bv, -0.5f * A))));
            const float m2 = fmaxf(fabsf(D),
                             fmaxf(fabsf(fmaf(h, E,  0.5f * D)),
                                   fabsf(fmaf(h, E, -0.5f * D))));

            maxtr = fmaxf(maxtr, fmaxf(mz + P22, m2 - P22));
        }

        // max over the 8 lanes owning this batch (xor-closed subgroups)
        #pragma unroll
        for (int off = 1; off < 8; off <<= 1)
            maxtr = fmaxf(maxtr, __shfl_xor_sync(0xFFFFFFFFu, maxtr, off));

        float cosv = (maxtr - 1.0f) * 0.5f;
        cosv = fminf(fmaxf(cosv, -1.0f + 1e-7f), 1.0f - 1e-7f);
        thetaSum += acosf(cosv);
    }

    // xor offsets {8,16} hit each 8-lane group exactly once -> sum of the
    // warp's 4 batch thetas per chunk, no overcount.
    #pragma unroll
    for (int off = 8; off < 32; off <<= 1)
        thetaSum += __shfl_xor_sync(0xFFFFFFFFu, thetaSum, off);

    if ((tid & 31) == 0) swarp[tid >> 5] = thetaSum;
    __syncthreads();

    if (tid == 0) {
        float s = 0.0f;
        #pragma unroll
        for (int i = 0; i < THREADS / 32; ++i) s += swarp[i];
        g_partials[cb] = s;
        __threadfence();
        unsigned int old = atomicAdd(&g_count, 1u);
        sIsLast = (old == (unsigned int)(NBLOCKS - 1));
    }
    __syncthreads();

    if (sIsLast) {
        __threadfence();   // acquire: see all blocks' partials
        float s = __ldg(&g_partials[tid]);          // 256 partials, L2-hot
        #pragma unroll
        for (int off = 16; off > 0; off >>= 1)
            s += __shfl_xor_sync(0xFFFFFFFFu, s, off);
        if ((tid & 31) == 0) swarp[tid >> 5] = s;
        __syncthreads();
        if (tid == 0) {
            float t = 0.0f;
            #pragma unroll
            for (int i = 0; i < THREADS / 32; ++i) t += swarp[i];
            out[0] = t / (float)B_TOTAL;
            g_count = 0;                            // reset for next replay
        }
    }
}

extern "C" void kernel_launch(void* const* d_in, const int* in_sizes, int n_in,
                              void* d_out, int out_size)
{
    const float* pred = (const float*)d_in[0];   // (B, C, 3, 3)
    const float* gt   = (const float*)d_in[1];   // (B, 3, 3)
    // d_in[2] = rot_mats: P622 rotations, folded into closed-form constants.
    float* out = (float*)d_out;

    // Idempotent attribute sets (host-side, once, not stream ops):
    // 74KB dynamic smem + pinned carveout so graph replays never reconfigure.
    cudaFuncSetAttribute(sym_loss_fused,
                         cudaFuncAttributeMaxDynamicSharedMemorySize, SMEM_DYN);
    cudaFuncSetAttribute(sym_loss_fused,
                         cudaFuncAttributePreferredSharedMemoryCarveout, 34);

    sym_loss_fused<<<NBLOCKS, THREADS, SMEM_DYN>>>(pred, gt, out);
}

// round 15
// speedup vs baseline: 2.5179x; 1.2250x over previous
#include <cuda_runtime.h>
#include <cuda_bf16.h>
#include <cstdint>

// SymmetryAwareLossLoop: mean over B of min over (C,S) geodesic angle.
// tr(R_pred (R_s R_gt)^T) = <R_s, P>, P = R_pred R_gt^T; P622 traces collapse
// to closed form (+/- pairs); acos monotone -> one acosf per batch group.
//
// R15 = exact R8 config (best wall 8.70us: grid=256, 64 batches/CTA,
// 2x32-batch TMA chunks all issued at t=0, fused fence+counter tail,
// 74KB dynamic smem, DEFAULT carveout -> 2 CTAs/SM). R14's carveout pin
// (34%) fit only 1 CTA/SM and regressed occ 21.6%->12.0%, 9.57->11.0us.
// Only retained tweak: __ldg on the L2-hot tail partials.

#define B_TOTAL   16384
#define C_CAND    32
#define THREADS   256
#define NBLOCKS   256
#define BATCH_PC  32                                  // batches per chunk
#define CHUNK_BYTES (BATCH_PC * C_CAND * 9 * 4)       // 36864
#define GT_BYTES    (2 * BATCH_PC * 9 * 4)            // 2304 (64 batches)
#define SMEM_DYN    (2 * CHUNK_BYTES + GT_BYTES)      // 76032

__device__ float        g_partials[NBLOCKS];
__device__ unsigned int g_count = 0;

extern __shared__ unsigned char s_dyn[];

__global__ __launch_bounds__(THREADS)
void sym_loss_fused(const float* __restrict__ pred,   // (B, C, 3, 3)
                    const float* __restrict__ gt,     // (B, 3, 3)
                    float* __restrict__ out)
{
    __shared__ alignas(8) unsigned long long s_mbar[2];
    __shared__ float swarp[THREADS / 32];
    __shared__ bool  sIsLast;

    const int tid = threadIdx.x;
    const int cb  = blockIdx.x;

    const uint32_t mb0 = (uint32_t)__cvta_generic_to_shared(&s_mbar[0]);
    const uint32_t mb1 = mb0 + 8u;

    if (tid == 0) {
        asm volatile("mbarrier.init.shared.b64 [%0], %1;" :: "r"(mb0), "r"(1u) : "memory");
        asm volatile("mbarrier.init.shared.b64 [%0], %1;" :: "r"(mb1), "r"(1u) : "memory");
    }
    __syncthreads();   // mbarriers visible before anyone waits

    if (tid == 0) {
        const uint32_t dp = (uint32_t)__cvta_generic_to_shared(s_dyn);
        const uint32_t dg = dp + 2 * CHUNK_BYTES;
        const float* srcp = pred + (size_t)cb * 2 * (CHUNK_BYTES / 4);
        const float* srcg = gt   + (size_t)cb * (GT_BYTES / 4);

        // chunk 0 + gt on mbar0; chunk 1 on mbar1. All in flight at t=0.
        asm volatile("mbarrier.arrive.expect_tx.shared.b64 _, [%0], %1;"
                     :: "r"(mb0), "r"((uint32_t)(CHUNK_BYTES + GT_BYTES)) : "memory");
        asm volatile("cp.async.bulk.shared::cta.global.mbarrier::complete_tx::bytes [%0], [%1], %2, [%3];"
                     :: "r"(dp), "l"(srcp), "r"((uint32_t)CHUNK_BYTES), "r"(mb0) : "memory");
        asm volatile("cp.async.bulk.shared::cta.global.mbarrier::complete_tx::bytes [%0], [%1], %2, [%3];"
                     :: "r"(dg), "l"(srcg), "r"((uint32_t)GT_BYTES), "r"(mb0) : "memory");

        asm volatile("mbarrier.arrive.expect_tx.shared.b64 _, [%0], %1;"
                     :: "r"(mb1), "r"((uint32_t)CHUNK_BYTES) : "memory");
        asm volatile("cp.async.bulk.shared::cta.global.mbarrier::complete_tx::bytes [%0], [%1], %2, [%3];"
                     :: "r"(dp + CHUNK_BYTES), "l"(srcp + CHUNK_BYTES / 4),
                        "r"((uint32_t)CHUNK_BYTES), "r"(mb1) : "memory");
    }

    const float h = 0.8660254037844386f;   // sin(pi/3)
    float thetaSum = 0.0f;

    #pragma unroll
    for (int k = 0; k < 2; ++k) {
        const uint32_t mb = k ? mb1 : mb0;
        asm volatile(
            "{\n\t"
            ".reg .pred P;\n\t"
            "WAIT_%=:\n\t"
            "mbarrier.try_wait.parity.shared.b64 P, [%0], %1;\n\t"
            "@P bra DONE_%=;\n\t"
            "bra WAIT_%=;\n\t"
            "DONE_%=:\n\t"
            "}"
            :: "r"(mb), "r"(0u) : "memory");

        // thread = quad of 4 candidates; chunk = 32 batches = 256 quads.
        const float4* __restrict__ sp =
            reinterpret_cast<const float4*>(s_dyn + k * CHUNK_BYTES + tid * 144);
        float4 v[9];
        #pragma unroll
        for (int i = 0; i < 9; ++i) v[i] = sp[i];
        const float* a = reinterpret_cast<const float*>(v);

        const float* __restrict__ gp = reinterpret_cast<const float*>(
            s_dyn + 2 * CHUNK_BYTES + (k * BATCH_PC + (tid >> 3)) * 36);
        float gr[9];
        #pragma unroll
        for (int i = 0; i < 9; ++i) gr[i] = gp[i];

        float maxtr = -4.0f;
        #pragma unroll
        for (int j = 0; j < 4; ++j) {
            const float p0 = a[9*j+0], p1 = a[9*j+1], p2 = a[9*j+2];
            const float p3 = a[9*j+3], p4 = a[9*j+4], p5 = a[9*j+5];
            const float p6 = a[9*j+6], p7 = a[9*j+7], p8 = a[9*j+8];

            const float P00 = fmaf(p0, gr[0], fmaf(p1, gr[1], p2 * gr[2]));
            const float P01 = fmaf(p0, gr[3], fmaf(p1, gr[4], p2 * gr[5]));
            const float P10 = fmaf(p3, gr[0], fmaf(p4, gr[1], p5 * gr[2]));
            const float P11 = fmaf(p3, gr[3], fmaf(p4, gr[4], p5 * gr[5]));
            const float P22 = fmaf(p6, gr[6], fmaf(p7, gr[7], p8 * gr[8]));

            const float A  = P00 + P11;
            const float Bv = P10 - P01;
            const float D  = P00 - P11;
            const float E  = P01 + P10;

            const float mz = fmaxf(fabsf(A),
                             fmaxf(fabsf(fmaf(h, Bv,  0.5f * A)),
                                   fabsf(fmaf(h, Bv, -0.5f * A))));
            const float m2 = fmaxf(fabsf(D),
                             fmaxf(fabsf(fmaf(h, E,  0.5f * D)),
                                   fabsf(fmaf(h, E, -0.5f * D))));

            maxtr = fmaxf(maxtr, fmaxf(mz + P22, m2 - P22));
        }

        // max over the 8 lanes owning this batch (xor-closed subgroups)
        #pragma unroll
        for (int off = 1; off < 8; off <<= 1)
            maxtr = fmaxf(maxtr, __shfl_xor_sync(0xFFFFFFFFu, maxtr, off));

        float cosv = (maxtr - 1.0f) * 0.5f;
        cosv = fminf(fmaxf(cosv, -1.0f + 1e-7f), 1.0f - 1e-7f);
        thetaSum += acosf(cosv);
    }

    // xor offsets {8,16} hit each 8-lane group exactly once -> sum of the
    // warp's 4 batch thetas per chunk, no overcount.
    #pragma unroll
    for (int off = 8; off < 32; off <<= 1)
        thetaSum += __shfl_xor_sync(0xFFFFFFFFu, thetaSum, off);

    if ((tid & 31) == 0) swarp[tid >> 5] = thetaSum;
    __syncthreads();

    if (tid == 0) {
        float s = 0.0f;
        #pragma unroll
        for (int i = 0; i < THREADS / 32; ++i) s += swarp[i];
        g_partials[cb] = s;
        __threadfence();
        unsigned int old = atomicAdd(&g_count, 1u);
        sIsLast = (old == (unsigned int)(NBLOCKS - 1));
    }
    __syncthreads();

    if (sIsLast) {
        __threadfence();   // acquire: see all blocks' partials
        float s = __ldg(&g_partials[tid]);          // 256 partials, L2-hot
        #pragma unroll
        for (int off = 16; off > 0; off >>= 1)
            s += __shfl_xor_sync(0xFFFFFFFFu, s, off);
        if ((tid & 31) == 0) swarp[tid >> 5] = s;
        __syncthreads();
        if (tid == 0) {
            float t = 0.0f;
            #pragma unroll
            for (int i = 0; i < THREADS / 32; ++i) t += swarp[i];
            out[0] = t / (float)B_TOTAL;
            g_count = 0;                            // reset for next replay
        }
    }
}

extern "C" void kernel_launch(void* const* d_in, const int* in_sizes, int n_in,
                              void* d_out, int out_size)
{
    const float* pred = (const float*)d_in[0];   // (B, C, 3, 3)
    const float* gt   = (const float*)d_in[1];   // (B, 3, 3)
    // d_in[2] = rot_mats: P622 rotations, folded into closed-form constants.
    float* out = (float*)d_out;

    // Idempotent attribute set (host-side, not a stream op): 74KB dynamic
    // smem. Default carveout -> 2 CTAs/SM (do NOT pin; see R14 regression).
    cudaFuncSetAttribute(sym_loss_fused,
                         cudaFuncAttributeMaxDynamicSharedMemorySize, SMEM_DYN);

    sym_loss_fused<<<NBLOCKS, THREADS, SMEM_DYN>>>(pred, gt, out);
}

// round 17
// speedup vs baseline: 2.5269x; 1.0036x over previous
#include <cuda_runtime.h>
#include <cuda_bf16.h>
#include <cstdint>

// SymmetryAwareLossLoop: mean over B of min over (C,S) geodesic angle.
// tr(R_pred (R_s R_gt)^T) = <R_s, P>, P = R_pred R_gt^T; P622 traces collapse
// to closed form (+/- pairs); acos monotone -> one acosf per batch group.
//
// R16 = R8/R15 config (grid=256, 64 batches/CTA, 2x32-batch TMA chunks all
// issued at t=0, 74KB smem, default carveout -> 2 CTAs/SM) with the exposed
// reduction tail collapsed: per-block theta-sums are accumulated into ONE
// u64 fixed-point atomic (scale 2^44; power-of-two multiply is exact in
// float, integer adds are exactly associative -> bitwise deterministic).
// Last block (fence+counter) converts and writes out; no 256-float gather.

#define B_TOTAL   16384
#define C_CAND    32
#define THREADS   256
#define NBLOCKS   256
#define BATCH_PC  32                                  // batches per chunk
#define CHUNK_BYTES (BATCH_PC * C_CAND * 9 * 4)       // 36864
#define GT_BYTES    (2 * BATCH_PC * 9 * 4)            // 2304 (64 batches)
#define SMEM_DYN    (2 * CHUNK_BYTES + GT_BYTES)      // 76032

// fixed-point scale 2^44; block sum <= 64*pi -> max ~201*2^44 ~ 3.5e15 per
// block, total < 2^63. Mean = total / (2^44 * 16384) = total / 2^58.
#define FX_SCALE    17592186044416.0f                 // 2^44
#define FX_INV_MEAN 3.469446951953614e-18             // 1.0 / 2^58 (double)

__device__ unsigned long long g_total = 0ull;
__device__ unsigned int       g_count = 0u;

extern __shared__ unsigned char s_dyn[];

__global__ __launch_bounds__(THREADS)
void sym_loss_fused(const float* __restrict__ pred,   // (B, C, 3, 3)
                    const float* __restrict__ gt,     // (B, 3, 3)
                    float* __restrict__ out)
{
    __shared__ alignas(8) unsigned long long s_mbar[2];
    __shared__ float swarp[THREADS / 32];

    const int tid = threadIdx.x;
    const int cb  = blockIdx.x;

    const uint32_t mb0 = (uint32_t)__cvta_generic_to_shared(&s_mbar[0]);
    const uint32_t mb1 = mb0 + 8u;

    if (tid == 0) {
        asm volatile("mbarrier.init.shared.b64 [%0], %1;" :: "r"(mb0), "r"(1u) : "memory");
        asm volatile("mbarrier.init.shared.b64 [%0], %1;" :: "r"(mb1), "r"(1u) : "memory");
    }
    __syncthreads();   // mbarriers visible before anyone waits

    if (tid == 0) {
        const uint32_t dp = (uint32_t)__cvta_generic_to_shared(s_dyn);
        const uint32_t dg = dp + 2 * CHUNK_BYTES;
        const float* srcp = pred + (size_t)cb * 2 * (CHUNK_BYTES / 4);
        const float* srcg = gt   + (size_t)cb * (GT_BYTES / 4);

        // chunk 0 + gt on mbar0; chunk 1 on mbar1. All in flight at t=0.
        asm volatile("mbarrier.arrive.expect_tx.shared.b64 _, [%0], %1;"
                     :: "r"(mb0), "r"((uint32_t)(CHUNK_BYTES + GT_BYTES)) : "memory");
        asm volatile("cp.async.bulk.shared::cta.global.mbarrier::complete_tx::bytes [%0], [%1], %2, [%3];"
                     :: "r"(dp), "l"(srcp), "r"((uint32_t)CHUNK_BYTES), "r"(mb0) : "memory");
        asm volatile("cp.async.bulk.shared::cta.global.mbarrier::complete_tx::bytes [%0], [%1], %2, [%3];"
                     :: "r"(dg), "l"(srcg), "r"((uint32_t)GT_BYTES), "r"(mb0) : "memory");

        asm volatile("mbarrier.arrive.expect_tx.shared.b64 _, [%0], %1;"
                     :: "r"(mb1), "r"((uint32_t)CHUNK_BYTES) : "memory");
        asm volatile("cp.async.bulk.shared::cta.global.mbarrier::complete_tx::bytes [%0], [%1], %2, [%3];"
                     :: "r"(dp + CHUNK_BYTES), "l"(srcp + CHUNK_BYTES / 4),
                        "r"((uint32_t)CHUNK_BYTES), "r"(mb1) : "memory");
    }

    const float h = 0.8660254037844386f;   // sin(pi/3)
    float thetaSum = 0.0f;

    #pragma unroll
    for (int k = 0; k < 2; ++k) {
        const uint32_t mb = k ? mb1 : mb0;
        asm volatile(
            "{\n\t"
            ".reg .pred P;\n\t"
            "WAIT_%=:\n\t"
            "mbarrier.try_wait.parity.shared.b64 P, [%0], %1;\n\t"
            "@P bra DONE_%=;\n\t"
            "bra WAIT_%=;\n\t"
            "DONE_%=:\n\t"
            "}"
            :: "r"(mb), "r"(0u) : "memory");

        // thread = quad of 4 candidates; chunk = 32 batches = 256 quads.
        const float4* __restrict__ sp =
            reinterpret_cast<const float4*>(s_dyn + k * CHUNK_BYTES + tid * 144);
        float4 v[9];
        #pragma unroll
        for (int i = 0; i < 9; ++i) v[i] = sp[i];
        const float* a = reinterpret_cast<const float*>(v);

        const float* __restrict__ gp = reinterpret_cast<const float*>(
            s_dyn + 2 * CHUNK_BYTES + (k * BATCH_PC + (tid >> 3)) * 36);
        float gr[9];
        #pragma unroll
        for (int i = 0; i < 9; ++i) gr[i] = gp[i];

        float maxtr = -4.0f;
        #pragma unroll
        for (int j = 0; j < 4; ++j) {
            const float p0 = a[9*j+0], p1 = a[9*j+1], p2 = a[9*j+2];
            const float p3 = a[9*j+3], p4 = a[9*j+4], p5 = a[9*j+5];
            const float p6 = a[9*j+6], p7 = a[9*j+7], p8 = a[9*j+8];

            const float P00 = fmaf(p0, gr[0], fmaf(p1, gr[1], p2 * gr[2]));
            const float P01 = fmaf(p0, gr[3], fmaf(p1, gr[4], p2 * gr[5]));
            const float P10 = fmaf(p3, gr[0], fmaf(p4, gr[1], p5 * gr[2]));
            const float P11 = fmaf(p3, gr[3], fmaf(p4, gr[4], p5 * gr[5]));
            const float P22 = fmaf(p6, gr[6], fmaf(p7, gr[7], p8 * gr[8]));

            const float A  = P00 + P11;
            const float Bv = P10 - P01;
            const float D  = P00 - P11;
            const float E  = P01 + P10;

            const float mz = fmaxf(fabsf(A),
                             fmaxf(fabsf(fmaf(h, Bv,  0.5f * A)),
                                   fabsf(fmaf(h, Bv, -0.5f * A))));
            const float m2 = fmaxf(fabsf(D),
                             fmaxf(fabsf(fmaf(h, E,  0.5f * D)),
                                   fabsf(fmaf(h, E, -0.5f * D))));

            maxtr = fmaxf(maxtr, fmaxf(mz + P22, m2 - P22));
        }

        // max over the 8 lanes owning this batch (xor-closed subgroups)
        #pragma unroll
        for (int off = 1; off < 8; off <<= 1)
            maxtr = fmaxf(maxtr, __shfl_xor_sync(0xFFFFFFFFu, maxtr, off));

        float cosv = (maxtr - 1.0f) * 0.5f;
        cosv = fminf(fmaxf(cosv, -1.0f + 1e-7f), 1.0f - 1e-7f);
        thetaSum += acosf(cosv);
    }

    // xor offsets {8,16} hit each 8-lane group exactly once -> sum of the
    // warp's 4 batch thetas per chunk, no overcount.
    #pragma unroll
    for (int off = 8; off < 32; off <<= 1)
        thetaSum += __shfl_xor_sync(0xFFFFFFFFu, thetaSum, off);

    if ((tid & 31) == 0) swarp[tid >> 5] = thetaSum;
    __syncthreads();

    if (tid == 0) {
        float s = 0.0f;
        #pragma unroll
        for (int i = 0; i < THREADS / 32; ++i) s += swarp[i];   // fixed order

        // Exact fixed-point conversion: *2^44 is an exponent shift (lossless
        // for float), __float2ll_rn exact. Integer adds are associative ->
        // order-independent, bitwise deterministic total.
        unsigned long long fx = (unsigned long long)__float2ll_rn(s * FX_SCALE);
        atomicAdd(&g_total, fx);
        __threadfence();
        unsigned int old = atomicAdd(&g_count, 1u);
        if (old == (unsigned int)(NBLOCKS - 1)) {
            // last block: all g_total adds are ordered before their g_count
            // increments (fence above), so an atomic read sees the full sum.
            unsigned long long tot = atomicAdd(&g_total, 0ull);
            out[0] = (float)((double)tot * FX_INV_MEAN);
            g_total = 0ull;          // reset for next graph replay
            g_count = 0u;
        }
    }
}

extern "C" void kernel_launch(void* const* d_in, const int* in_sizes, int n_in,
                              void* d_out, int out_size)
{
    const float* pred = (const float*)d_in[0];   // (B, C, 3, 3)
    const float* gt   = (const float*)d_in[1];   // (B, 3, 3)
    // d_in[2] = rot_mats: P622 rotations, folded into closed-form constants.
    float* out = (float*)d_out;

    // Idempotent attribute set (host-side, not a stream op): 74KB dynamic
    // smem. Default carveout -> 2 CTAs/SM (do NOT pin; see R14 regression).
    cudaFuncSetAttribute(sym_loss_fused,
                         cudaFuncAttributeMaxDynamicSharedMemorySize, SMEM_DYN);

    sym_loss_fused<<<NBLOCKS, THREADS, SMEM_DYN>>>(pred, gt, out);
}